// round 16
// baseline (speedup 1.0000x reference)
#include <cuda_runtime.h>
#include <cuda_fp16.h>
#include <math.h>
#include <cstdint>

// ---------------------------------------------------------------------------
// SlotAttention: b=32, n=1024, c=256, d=256, S=8 slots, 3 iters.
// fp16 m16n8k16 mma.sync; fp16 kv + fp16 updp partials.
// attn: batched k-fragment loads (chain depth 2), dots mma, updates mma.
// ---------------------------------------------------------------------------
#define NTOK 1024
#define ITERS 3
#define TOKROWS 32768
#define SROWS 256
#define SCALE_F 0.0625f
#define EPS_F 1e-8f
#define NCHUNK 16               // attn j-chunks of 64

// scratch arena (floats)
#define OFF_KV     0                                  // half[32768*512]
#define OFF_SLOTS  (OFF_KV + TOKROWS*256)
#define OFF_GBUF   (OFF_SLOTS + SROWS*256)
#define OFF_Q      (OFF_GBUF + SROWS*256)
#define OFF_H1     (OFF_Q + SROWS*256)                // 256*1024
#define OFF_UPDP   (OFF_H1 + SROWS*1024)              // half[16*256*256]
#define OFF_RSP    (OFF_UPDP + NCHUNK*SROWS*128)      // 16*256
#define OFF_S1KV   (OFF_RSP + NCHUNK*SROWS)           // 512
#define OFF_S2KV   (OFF_S1KV + 512)
#define OFF_WQP    (OFF_S2KV + 512)                   // 256*256 row-major
#define OFF_S1Q    (OFF_WQP + 256*256)
#define OFF_S2Q    (OFF_S1Q + 256)
#define OFF_W1P    (OFF_S2Q + 256)                    // 1024*256
#define OFF_S1M    (OFF_W1P + 1024*256)
#define OFF_S2M    (OFF_S1M + 1024)
#define SCRATCH_FLOATS (OFF_S2M + 1024)

__device__ __align__(16) float g_scratch[SCRATCH_FLOATS];
__device__ __align__(16) __half g_wb[512 * 256];

__device__ __forceinline__ float warp_sum(float v) {
#pragma unroll
    for (int o = 16; o > 0; o >>= 1) v += __shfl_xor_sync(0xffffffffu, v, o);
    return v;
}
__device__ __forceinline__ float grp8_sum(float v) {
    v += __shfl_xor_sync(0xffffffffu, v, 4);
    v += __shfl_xor_sync(0xffffffffu, v, 2);
    v += __shfl_xor_sync(0xffffffffu, v, 1);
    return v;
}
__device__ __forceinline__ float sigmoidf_(float x) { return 1.0f / (1.0f + __expf(-x)); }

__device__ __forceinline__ void mmaf16(float* d, const unsigned* a, const unsigned* b) {
    asm volatile("mma.sync.aligned.m16n8k16.row.col.f32.f16.f16.f32 "
        "{%0,%1,%2,%3}, {%4,%5,%6,%7}, {%8,%9}, {%0,%1,%2,%3};"
        : "+f"(d[0]), "+f"(d[1]), "+f"(d[2]), "+f"(d[3])
        : "r"(a[0]), "r"(a[1]), "r"(a[2]), "r"(a[3]), "r"(b[0]), "r"(b[1]));
}
__device__ __forceinline__ uint32_t packh2(float x, float y) {
    __half2 h = __floats2half2_rn(x, y);
    return *(uint32_t*)&h;
}

// ---------------------------------------------------------------------------
// setup: all weight preps + slot init in ONE kernel (grid 480).
// ---------------------------------------------------------------------------
__global__ void setup_kernel(
    const float* __restrict__ Wk, const float* __restrict__ Wv,
    const float* __restrict__ ln_in_g, const float* __restrict__ ln_in_b,
    __half* __restrict__ wb, float* __restrict__ S1kv, float* __restrict__ S2kv,
    const float* __restrict__ Wq, const float* __restrict__ ln_s_g, const float* __restrict__ ln_s_b,
    float* __restrict__ Wqp, float* __restrict__ S1q, float* __restrict__ S2q,
    const float* __restrict__ W1, const float* __restrict__ ln_ff_g, const float* __restrict__ ln_ff_b,
    float* __restrict__ W1p, float* __restrict__ S1m, float* __restrict__ S2m,
    const float* __restrict__ mu, const float* __restrict__ ls,
    const float* __restrict__ noise, float* __restrict__ slots) {
    int blk = blockIdx.x;
    int w = threadIdx.x >> 5, lane = threadIdx.x & 31;
    if (blk < 64) {
        int n = blk * 8 + w;
        const float* src = (n < 256) ? Wk + (size_t)n * 256 : Wv + (size_t)(n - 256) * 256;
        float s1 = 0.f, s2 = 0.f;
#pragma unroll
        for (int u = 0; u < 8; u++) {
            int c = u * 32 + lane;
            __half hf = __float2half(src[c] * ln_in_g[c]);
            wb[(size_t)n * 256 + c] = hf;
            s1 += __half2float(hf);
            s2 += src[c] * ln_in_b[c];
        }
        s1 = warp_sum(s1); s2 = warp_sum(s2);
        if (lane == 0) { S1kv[n] = s1; S2kv[n] = s2; }
    } else if (blk < 96) {
        int n = (blk - 64) * 8 + w;
        float s1 = 0.f, s2 = 0.f;
#pragma unroll
        for (int u = 0; u < 8; u++) {
            int c = u * 32 + lane;
            float wv = Wq[(size_t)n * 256 + c] * ln_s_g[c];
            Wqp[(size_t)n * 256 + c] = wv;
            s1 += wv;
            s2 += Wq[(size_t)n * 256 + c] * ln_s_b[c];
        }
        s1 = warp_sum(s1); s2 = warp_sum(s2);
        if (lane == 0) { S1q[n] = s1; S2q[n] = s2; }
    } else if (blk < 224) {
        int n = (blk - 96) * 8 + w;
        float s1 = 0.f, s2 = 0.f;
#pragma unroll
        for (int u = 0; u < 8; u++) {
            int c = u * 32 + lane;
            float wv = W1[(size_t)n * 256 + c] * ln_ff_g[c];
            W1p[(size_t)n * 256 + c] = wv;
            s1 += wv;
            s2 += W1[(size_t)n * 256 + c] * ln_ff_b[c];
        }
        s1 = warp_sum(s1); s2 = warp_sum(s2);
        if (lane == 0) { S1m[n] = s1; S2m[n] = s2; }
    } else {
        int idx = (blk - 224) * 256 + threadIdx.x;
        int d = idx & 255;
        slots[idx] = mu[d] + __expf(ls[d]) * noise[idx];
    }
}

// ---------------------------------------------------------------------------
// KV GEMM: C_fp16[32768, 512] = LN(x) @ [W'k;W'v]^T.
// BM=128 BN=64 BK=32, 2 CTAs/SM; fp16 m16n8k16; LN-fold epilogue, fp16 out.
// ---------------------------------------------------------------------------
__global__ __launch_bounds__(256, 2) void kv_mma_kernel(
    const float* __restrict__ x, const __half* __restrict__ wb,
    const float* __restrict__ S1, const float* __restrict__ S2,
    __half* __restrict__ C) {
    __shared__ uint32_t As[128][20];
    __shared__ uint32_t Bs[64][20];
    __shared__ float rowm[128], rowr[128];
    int t = threadIdx.x;
    int bm = blockIdx.y * 128, bn = blockIdx.x * 64;
    int w = t >> 5, lane = t & 31;
    int m0 = (w >> 2) * 64, n0 = (w & 3) * 16;
    int g = lane >> 2, tig = lane & 3;
    float acc[4][2][4];
#pragma unroll
    for (int a = 0; a < 4; a++)
#pragma unroll
        for (int bq = 0; bq < 2; bq++)
#pragma unroll
            for (int c = 0; c < 4; c++) acc[a][bq][c] = 0.f;

    int lm = t >> 3;
    int lkf = (t & 7) * 4;
    int lku = (t & 7) * 2;

    float4 ar[4]; uint2 br[2];
    float sA[4] = {0.f, 0.f, 0.f, 0.f}, s2A[4] = {0.f, 0.f, 0.f, 0.f};
#pragma unroll
    for (int r = 0; r < 4; r++)
        ar[r] = *(const float4*)(x + (size_t)(bm + r * 32 + lm) * 256 + lkf);
#pragma unroll
    for (int r = 0; r < 2; r++)
        br[r] = *(const uint2*)(wb + (size_t)(bn + r * 32 + lm) * 256 + lkf);

    for (int it = 0; it < 8; it++) {
#pragma unroll
        for (int r = 0; r < 4; r++) {
            sA[r] += ar[r].x + ar[r].y + ar[r].z + ar[r].w;
            s2A[r] += ar[r].x * ar[r].x + ar[r].y * ar[r].y + ar[r].z * ar[r].z + ar[r].w * ar[r].w;
        }
        __syncthreads();
#pragma unroll
        for (int r = 0; r < 4; r++) {
            int m = r * 32 + lm;
            As[m][lku + 0] = packh2(ar[r].x, ar[r].y);
            As[m][lku + 1] = packh2(ar[r].z, ar[r].w);
        }
#pragma unroll
        for (int r = 0; r < 2; r++) {
            int m = r * 32 + lm;
            Bs[m][lku + 0] = br[r].x;
            Bs[m][lku + 1] = br[r].y;
        }
        __syncthreads();
        if (it < 7) {
            int c = (it + 1) * 32 + lkf;
#pragma unroll
            for (int r = 0; r < 4; r++)
                ar[r] = *(const float4*)(x + (size_t)(bm + r * 32 + lm) * 256 + c);
#pragma unroll
            for (int r = 0; r < 2; r++)
                br[r] = *(const uint2*)(wb + (size_t)(bn + r * 32 + lm) * 256 + c);
        }
#pragma unroll
        for (int ks = 0; ks < 2; ks++) {
            unsigned a[4][4], b[2][2];
#pragma unroll
            for (int mt = 0; mt < 4; mt++) {
                int mr = m0 + mt * 16 + g;
                a[mt][0] = As[mr][ks * 8 + tig];
                a[mt][1] = As[mr + 8][ks * 8 + tig];
                a[mt][2] = As[mr][ks * 8 + tig + 4];
                a[mt][3] = As[mr + 8][ks * 8 + tig + 4];
            }
#pragma unroll
            for (int nt = 0; nt < 2; nt++) {
                int nr = n0 + nt * 8 + g;
                b[nt][0] = Bs[nr][ks * 8 + tig];
                b[nt][1] = Bs[nr][ks * 8 + tig + 4];
            }
#pragma unroll
            for (int mt = 0; mt < 4; mt++)
#pragma unroll
                for (int nt = 0; nt < 2; nt++)
                    mmaf16(acc[mt][nt], a[mt], b[nt]);
        }
    }
#pragma unroll
    for (int r = 0; r < 4; r++) {
        float s = grp8_sum(sA[r]);
        float s2 = grp8_sum(s2A[r]);
        if ((t & 7) == 0) {
            float m = s * (1.0f / 256.0f);
            float var = s2 * (1.0f / 256.0f) - m * m;
            rowm[r * 32 + lm] = m;
            rowr[r * 32 + lm] = rsqrtf(var + 1e-5f);
        }
    }
    __syncthreads();
#pragma unroll
    for (int mt = 0; mt < 4; mt++)
#pragma unroll
        for (int nt = 0; nt < 2; nt++) {
            int lr = m0 + mt * 16 + g;
            int col = bn + n0 + nt * 8 + tig * 2;
            float s1a = S1[col], s1b = S1[col + 1], s2a = S2[col], s2b = S2[col + 1];
            float m0v = rowm[lr], r0v = rowr[lr];
            float m1v = rowm[lr + 8], r1v = rowr[lr + 8];
            uint32_t o0 = packh2(r0v * acc[mt][nt][0] - r0v * m0v * s1a + s2a,
                                 r0v * acc[mt][nt][1] - r0v * m0v * s1b + s2b);
            uint32_t o1 = packh2(r1v * acc[mt][nt][2] - r1v * m1v * s1a + s2a,
                                 r1v * acc[mt][nt][3] - r1v * m1v * s1b + s2b);
            *(uint32_t*)(C + (size_t)(bm + lr) * 512 + col) = o0;
            *(uint32_t*)(C + (size_t)(bm + lr + 8) * 512 + col) = o1;
        }
}

// ---------------------------------------------------------------------------
// gemm16: 16-row x NC-col tiles, 256 threads, register-prefetched BK=32.
// ---------------------------------------------------------------------------
template<int NC, bool LNF, bool RELU, bool ADDOUT, bool QSC>
__global__ __launch_bounds__(256) void gemm16_kernel(
    const float* __restrict__ A, const float* __restrict__ B,
    const float* __restrict__ S1, const float* __restrict__ S2,
    const float* __restrict__ bias, const float* __restrict__ addsrc,
    float* __restrict__ C, int N, int K) {
    constexpr int CPT = NC / 32;
    __shared__ float As[16][34];
    __shared__ float Bs[NC][34];
    __shared__ float rowm[16], rowr[16];
    int t = threadIdx.x;
    int bm = blockIdx.y * 16, bn = blockIdx.x * NC;
    if (LNF) {
        int w = t >> 5, lane = t & 31;
#pragma unroll
        for (int rr = 0; rr < 2; rr++) {
            int row = w * 2 + rr;
            const float* p = A + (size_t)(bm + row) * 256;
            float s = 0.f, s2 = 0.f;
#pragma unroll
            for (int u = 0; u < 8; u++) { float v = p[lane + u * 32]; s += v; s2 += v * v; }
            s = warp_sum(s); s2 = warp_sum(s2);
            if (lane == 0) {
                float m = s * (1.0f / 256.0f);
                float var = s2 * (1.0f / 256.0f) - m * m;
                rowm[row] = m; rowr[row] = rsqrtf(var + 1e-5f);
            }
        }
    }
    int ar = t >> 4, ak = (t & 15) * 2;
    int brr = t >> 3, bk = (t & 7) * 4;
    int tr = t >> 5, tc = t & 31;
    float acc[2][CPT];
#pragma unroll
    for (int r = 0; r < 2; r++)
#pragma unroll
        for (int c = 0; c < CPT; c++) acc[r][c] = 0.f;

    float2 pa = *(const float2*)(A + (size_t)(bm + ar) * K + ak);
    float4 pb[CPT];
#pragma unroll
    for (int c = 0; c < CPT; c++)
        pb[c] = *(const float4*)(B + (size_t)(bn + c * 32 + brr) * K + bk);

    int KT = K >> 5;
    for (int kt = 0; kt < KT; kt++) {
        __syncthreads();
        As[ar][ak] = pa.x; As[ar][ak + 1] = pa.y;
#pragma unroll
        for (int c = 0; c < CPT; c++) {
            Bs[c * 32 + brr][bk + 0] = pb[c].x; Bs[c * 32 + brr][bk + 1] = pb[c].y;
            Bs[c * 32 + brr][bk + 2] = pb[c].z; Bs[c * 32 + brr][bk + 3] = pb[c].w;
        }
        __syncthreads();
        if (kt + 1 < KT) {
            int k0 = (kt + 1) * 32;
            pa = *(const float2*)(A + (size_t)(bm + ar) * K + k0 + ak);
#pragma unroll
            for (int c = 0; c < CPT; c++)
                pb[c] = *(const float4*)(B + (size_t)(bn + c * 32 + brr) * K + k0 + bk);
        }
#pragma unroll
        for (int kk = 0; kk < 32; kk += 2) {
            float2 a0 = *(const float2*)&As[tr][kk];
            float2 a1 = *(const float2*)&As[tr + 8][kk];
#pragma unroll
            for (int c = 0; c < CPT; c++) {
                float2 b2 = *(const float2*)&Bs[tc + c * 32][kk];
                acc[0][c] += a0.x * b2.x + a0.y * b2.y;
                acc[1][c] += a1.x * b2.x + a1.y * b2.y;
            }
        }
    }
#pragma unroll
    for (int r = 0; r < 2; r++) {
        int lr = tr + r * 8;
        int row = bm + lr;
#pragma unroll
        for (int c = 0; c < CPT; c++) {
            int col = bn + c * 32 + tc;
            float v = acc[r][c];
            if (LNF) { float m = rowm[lr], rs = rowr[lr]; v = rs * v - rs * m * S1[col] + S2[col]; }
            if (bias) v += bias[col];
            if (RELU) v = fmaxf(v, 0.f);
            if (QSC) v *= SCALE_F;
            if (ADDOUT) v += addsrc[(size_t)row * N + col];
            C[(size_t)row * N + col] = v;
        }
    }
}

// ---------------------------------------------------------------------------
// attention: dots mma (k fragments loaded in 2 batches of 16 independent LDG),
// lane-parallel softmax, updates mma, fp16 updp out.
// grid (32 batches, 16 j-chunks of 64).
// ---------------------------------------------------------------------------
__global__ __launch_bounds__(256) void attn2_kernel(
    const float* __restrict__ qbuf, const __half* __restrict__ kv,
    __half* __restrict__ updp, float* __restrict__ rsp) {
    __shared__ uint32_t qs[8][132];          // fp16x2 pairs, row = slot
    __shared__ uint32_t attnT[8][34];        // fp16x2 j-pairs, row = slot
    __shared__ uint32_t vT[256][34];         // fp16x2 j-pairs, row = col
    __shared__ float rswarp[8][8];
    int b = blockIdx.x, jc = blockIdx.y;
    int t = threadIdx.x, w = t >> 5, lane = t & 31;
    int g = lane >> 2, tig = lane & 3;

    // stage q as fp16 pairs
    {
        int row = t >> 5, c8 = (t & 31) * 8;
        const float* qrow = qbuf + (size_t)(b * 8 + row) * 256 + c8;
        float4 f0 = *(const float4*)(qrow);
        float4 f1 = *(const float4*)(qrow + 4);
        int c4 = c8 >> 1;
        qs[row][c4 + 0] = packh2(f0.x, f0.y);
        qs[row][c4 + 1] = packh2(f0.z, f0.w);
        qs[row][c4 + 2] = packh2(f1.x, f1.y);
        qs[row][c4 + 3] = packh2(f1.z, f1.w);
    }
    // stage vT: thread t = col; pack j-pairs
    {
        const __half* vb = kv + ((size_t)b * NTOK + jc * 64) * 512 + 256 + t;
#pragma unroll 8
        for (int j2 = 0; j2 < 32; j2++) {
            __half lo = vb[(size_t)(2 * j2) * 512];
            __half hi = vb[(size_t)(2 * j2 + 1) * 512];
            __half2 p = __halves2half2(lo, hi);
            vT[t][j2] = *(uint32_t*)&p;
        }
    }
    __syncthreads();

    // dots mma: warp w -> j-tile [w*8, w*8+8); k fragments in 2 batches of 16.
    {
        const uint32_t* kbase = (const uint32_t*)(kv + ((size_t)b * NTOK + jc * 64 + w * 8) * 512);
        float c[4] = {0.f, 0.f, 0.f, 0.f};
#pragma unroll
        for (int h = 0; h < 2; h++) {
            uint32_t kr[16];
#pragma unroll
            for (int ks = 0; ks < 8; ks++) {
                kr[ks * 2 + 0] = kbase[(size_t)g * 256 + (h * 8 + ks) * 8 + tig];
                kr[ks * 2 + 1] = kbase[(size_t)g * 256 + (h * 8 + ks) * 8 + tig + 4];
            }
#pragma unroll
            for (int ks = 0; ks < 8; ks++) {
                unsigned a[4], bfr[2];
                a[0] = qs[g][(h * 8 + ks) * 8 + tig];
                a[1] = 0u;
                a[2] = qs[g][(h * 8 + ks) * 8 + tig + 4];
                a[3] = 0u;
                bfr[0] = kr[ks * 2];
                bfr[1] = kr[ks * 2 + 1];
                mmaf16(c, a, bfr);
            }
        }
        // softmax over slots: reduce across lanes varying g (xor 4,8,16)
        float m0 = c[0], m1 = c[1];
#pragma unroll
        for (int o = 4; o <= 16; o <<= 1) {
            m0 = fmaxf(m0, __shfl_xor_sync(0xffffffffu, m0, o));
            m1 = fmaxf(m1, __shfl_xor_sync(0xffffffffu, m1, o));
        }
        float e0 = __expf(c[0] - m0), e1 = __expf(c[1] - m1);
        float s0 = e0, s1 = e1;
#pragma unroll
        for (int o = 4; o <= 16; o <<= 1) {
            s0 += __shfl_xor_sync(0xffffffffu, s0, o);
            s1 += __shfl_xor_sync(0xffffffffu, s1, o);
        }
        float a0 = e0 / s0 + EPS_F;
        float a1 = e1 / s1 + EPS_F;
        __half2 ah = __floats2half2_rn(a0, a1);
        attnT[g][w * 4 + tig] = *(uint32_t*)&ah;
        // row sums from ROUNDED values (cancels fp16 quantization in u)
        float2 arf = __half22float2(ah);
        float rsa = arf.x + arf.y;
        rsa += __shfl_xor_sync(0xffffffffu, rsa, 1);
        rsa += __shfl_xor_sync(0xffffffffu, rsa, 2);
        if (tig == 0) rswarp[w][g] = rsa;
    }
    __syncthreads();

    // updates mma: out[col][slot], warp w -> m-tiles at w*32, w*32+16; K=64.
    {
        size_t outbase = (size_t)jc * SROWS + b * 8;
#pragma unroll
        for (int tt = 0; tt < 2; tt++) {
            int m0r = w * 32 + tt * 16;
            float c[4] = {0.f, 0.f, 0.f, 0.f};
#pragma unroll
            for (int ks = 0; ks < 4; ks++) {
                unsigned a[4], bfr[2];
                a[0] = vT[m0r + g][ks * 8 + tig];
                a[1] = vT[m0r + g + 8][ks * 8 + tig];
                a[2] = vT[m0r + g][ks * 8 + tig + 4];
                a[3] = vT[m0r + g + 8][ks * 8 + tig + 4];
                bfr[0] = attnT[g][ks * 8 + tig];
                bfr[1] = attnT[g][ks * 8 + tig + 4];
                mmaf16(c, a, bfr);
            }
            // lane (g,tig): cols m0r+g, m0r+g+8; slots 2tig, 2tig+1
            updp[(outbase + 2 * tig) * 256 + m0r + g] = __float2half(c[0]);
            updp[(outbase + 2 * tig + 1) * 256 + m0r + g] = __float2half(c[1]);
            updp[(outbase + 2 * tig) * 256 + m0r + g + 8] = __float2half(c[2]);
            updp[(outbase + 2 * tig + 1) * 256 + m0r + g + 8] = __float2half(c[3]);
        }
        if (t < 8) {
            float r = 0.f;
#pragma unroll
            for (int ww = 0; ww < 8; ww++) r += rswarp[ww][t];
            rsp[jc * SROWS + b * 8 + t] = r;
        }
    }
}

// ---------------------------------------------------------------------------
// GRU, 16x32 units, fp16 updp reduction inline. grid (8, 16) = 128 blocks.
// ---------------------------------------------------------------------------
__global__ __launch_bounds__(256) void gru16_kernel(
    const __half* __restrict__ updp, const float* __restrict__ rsp,
    const float* __restrict__ slots,
    const float* __restrict__ wih, const float* __restrict__ whh,
    const float* __restrict__ bih, const float* __restrict__ bhh,
    float* __restrict__ out) {
    __shared__ float Au[16][34], Ah[16][34];
    __shared__ float Bg[6][32][34];
    __shared__ float invrs[16];
    int t = threadIdx.x;
    int bm = blockIdx.y * 16, bn = blockIdx.x * 32;
    if (t < 16) {
        float rs = 0.f;
#pragma unroll
        for (int p = 0; p < NCHUNK; p++) rs += rsp[p * 256 + bm + t];
        invrs[t] = 1.0f / rs;
    }
    int ar = t >> 4, ak = (t & 15) * 2;
    int brr = t >> 3, bk = (t & 7) * 4;
    int tr = t >> 5, tc = t & 31;
    float acc[6][2];
#pragma unroll
    for (int g = 0; g < 6; g++) { acc[g][0] = 0.f; acc[g][1] = 0.f; }

    for (int kt = 0; kt < 8; kt++) {
        int k0 = kt * 32;
        __syncthreads();
        {
            size_t base = (size_t)(bm + ar) * 256 + k0 + ak;
            float sx = 0.f, sy = 0.f;
#pragma unroll
            for (int p = 0; p < NCHUNK; p++) {
                uint32_t raw = *(const uint32_t*)(updp + (size_t)p * 65536 + base);
                float2 f = __half22float2(*(__half2*)&raw);
                sx += f.x; sy += f.y;
            }
            float iv = invrs[ar];
            Au[ar][ak] = sx * iv; Au[ar][ak + 1] = sy * iv;
            float2 h2 = *(const float2*)(slots + base);
            Ah[ar][ak] = h2.x; Ah[ar][ak + 1] = h2.y;
#pragma unroll
            for (int g = 0; g < 6; g++) {
                const float* W = (g < 3) ? wih : whh;
                float4 w4 = *(const float4*)(W + (size_t)((g % 3) * 256 + bn + brr) * 256 + k0 + bk);
                Bg[g][brr][bk + 0] = w4.x; Bg[g][brr][bk + 1] = w4.y;
                Bg[g][brr][bk + 2] = w4.z; Bg[g][brr][bk + 3] = w4.w;
            }
        }
        __syncthreads();
#pragma unroll
        for (int kk = 0; kk < 32; kk += 2) {
            float2 u0 = *(const float2*)&Au[tr][kk];
            float2 u1 = *(const float2*)&Au[tr + 8][kk];
            float2 h0 = *(const float2*)&Ah[tr][kk];
            float2 h1v = *(const float2*)&Ah[tr + 8][kk];
#pragma unroll
            for (int g = 0; g < 6; g++) {
                float2 b2 = *(const float2*)&Bg[g][tc][kk];
                if (g < 3) {
                    acc[g][0] += u0.x * b2.x + u0.y * b2.y;
                    acc[g][1] += u1.x * b2.x + u1.y * b2.y;
                } else {
                    acc[g][0] += h0.x * b2.x + h0.y * b2.y;
                    acc[g][1] += h1v.x * b2.x + h1v.y * b2.y;
                }
            }
        }
    }
    int col = bn + tc;
#pragma unroll
    for (int r = 0; r < 2; r++) {
        int row = bm + tr + r * 8;
        float ir = acc[0][r] + bih[col];
        float iz = acc[1][r] + bih[col + 256];
        float in_ = acc[2][r] + bih[col + 512];
        float hr = acc[3][r] + bhh[col];
        float hz = acc[4][r] + bhh[col + 256];
        float hn = acc[5][r] + bhh[col + 512];
        float rg = sigmoidf_(ir + hr);
        float z = sigmoidf_(iz + hz);
        float nn = tanhf(in_ + rg * hn);
        float h = slots[(size_t)row * 256 + col];
        out[(size_t)row * 256 + col] = (1.0f - z) * nn + z * h;
    }
}

extern "C" void kernel_launch(void* const* d_in, const int* in_sizes, int n_in,
                              void* d_out, int out_size) {
    const float* inputs    = (const float*)d_in[0];
    const float* noise     = (const float*)d_in[1];
    const float* slots_mu  = (const float*)d_in[2];
    const float* slots_ls  = (const float*)d_in[3];
    const float* Wq        = (const float*)d_in[4];
    const float* Wk        = (const float*)d_in[5];
    const float* Wv        = (const float*)d_in[6];
    const float* gru_wih   = (const float*)d_in[7];
    const float* gru_whh   = (const float*)d_in[8];
    const float* gru_bih   = (const float*)d_in[9];
    const float* gru_bhh   = (const float*)d_in[10];
    const float* mlp_w1    = (const float*)d_in[11];
    const float* mlp_b1    = (const float*)d_in[12];
    const float* mlp_w2    = (const float*)d_in[13];
    const float* mlp_b2    = (const float*)d_in[14];
    const float* ln_in_g   = (const float*)d_in[15];
    const float* ln_in_b   = (const float*)d_in[16];
    const float* ln_s_g    = (const float*)d_in[17];
    const float* ln_s_b    = (const float*)d_in[18];
    const float* ln_ff_g   = (const float*)d_in[19];
    const float* ln_ff_b   = (const float*)d_in[20];

    float* S = nullptr;
    cudaGetSymbolAddress((void**)&S, g_scratch);
    __half* wb = nullptr;
    cudaGetSymbolAddress((void**)&wb, g_wb);
    __half* kv    = (__half*)(S + OFF_KV);
    float* slots  = S + OFF_SLOTS;
    float* gbuf   = S + OFF_GBUF;
    float* qbuf   = S + OFF_Q;
    float* h1     = S + OFF_H1;
    __half* updp  = (__half*)(S + OFF_UPDP);
    float* rsp    = S + OFF_RSP;
    float* S1kv   = S + OFF_S1KV;
    float* S2kv   = S + OFF_S2KV;
    float* Wqp    = S + OFF_WQP;
    float* S1q    = S + OFF_S1Q;
    float* S2q    = S + OFF_S2Q;
    float* W1p    = S + OFF_W1P;
    float* S1m    = S + OFF_S1M;
    float* S2m    = S + OFF_S2M;

    // 0: all preps + slot init
    setup_kernel<<<480, 256>>>(Wk, Wv, ln_in_g, ln_in_b, wb, S1kv, S2kv,
                               Wq, ln_s_g, ln_s_b, Wqp, S1q, S2q,
                               mlp_w1, ln_ff_g, ln_ff_b, W1p, S1m, S2m,
                               slots_mu, slots_ls, noise, slots);
    // 1: KV projection (fp16 out, 2 CTAs/SM)
    kv_mma_kernel<<<dim3(8, 256), 256>>>(inputs, wb, S1kv, S2kv, kv);

    for (int it = 0; it < ITERS; it++) {
        // q = LN(slots)@W'q * SCALE   (launch 2 on it0)
        gemm16_kernel<32, true, false, false, true><<<dim3(8, 16), 256>>>(
            slots, Wqp, S1q, S2q, nullptr, nullptr, qbuf, 256, 256);
        // attn partials                (launch 3 on it0 -> profiled)
        attn2_kernel<<<dim3(32, NCHUNK), 256>>>(qbuf, kv, updp, rsp);
        // GRU (fp16 updp reduce inline)
        gru16_kernel<<<dim3(8, 16), 256>>>(updp, rsp, slots,
            gru_wih, gru_whh, gru_bih, gru_bhh, gbuf);
        // mlp1 = relu(LN(gbuf)@W'1 + b1)
        gemm16_kernel<64, true, true, false, false><<<dim3(16, 16), 256>>>(
            gbuf, W1p, S1m, S2m, mlp_b1, nullptr, h1, 1024, 256);
        // mlp2 = h1@W2 + b2 + gbuf
        float* outp = (it == ITERS - 1) ? (float*)d_out : slots;
        gemm16_kernel<32, false, false, true, false><<<dim3(8, 16), 256>>>(
            h1, mlp_w2, nullptr, nullptr, mlp_b2, gbuf, outp, 256, 1024);
    }
}